// round 6
// baseline (speedup 1.0000x reference)
#include <cuda_runtime.h>
#include <math.h>

// Problem constants
#define T_SEQ 4096
#define HID   1024
#define G4    4096   // 4*HID
#define KDIM  1024   // E == H

#define REC_NC 128   // recurrent CTAs (1 per SM, all co-resident)

// ---------------- device scratch (static, no allocations) ----------------
__device__ float g_pre[2][T_SEQ][G4];                 // input projections (128 MB)
__device__ float g_hseq[2][T_SEQ][HID];               // per-layer hidden sequence
// LL-style publish buffers: per unit an 8B packet {h, tag}; per branch, double-buffered
__device__ __align__(8) float2 g_pubA[2][HID];
__device__ __align__(8) float2 g_pubB[2][HID];

// ---------------- tag reset (before each recurrent launch / replay) ------
__global__ void reset_pub() {
    float2 z = make_float2(0.f, 0.f);
    int i = threadIdx.x;                  // 512 threads
    #pragma unroll
    for (int j = 0; j < 4; ++j) {
        ((float2*)g_pubA)[i + j * 512] = z;
        ((float2*)g_pubB)[i + j * 512] = z;
    }
}

// ---------------- SGEMM: pre[b][t][r] = sum_k A_b[t][k]*W[r][k] + bias ----
// Ping-pong SMEM double buffering: one __syncthreads per k-tile.
#define BM 128
#define BN 128
#define BK 8

__global__ void __launch_bounds__(256, 2)
sgemm_nt_bias(const float* __restrict__ A0, const float* __restrict__ A1,
              int from_hseq,
              const float* __restrict__ W,
              const float* __restrict__ bi, const float* __restrict__ bh)
{
    __shared__ float As[2][BK][BM];
    __shared__ float Bs[2][BK][BN];

    const int z = blockIdx.z;   // branch
    const float* A = from_hseq ? &g_hseq[z][0][0] : (z ? A1 : A0);
    float* C = &g_pre[z][0][0];

    const int m0 = blockIdx.y * BM;
    const int n0 = blockIdx.x * BN;
    const int tid = threadIdx.x;

    const int lr = tid >> 1;          // 0..127 row within tile
    const int lc = (tid & 1) * 4;     // 0 or 4 within k-tile

    float acc[8][8];
    #pragma unroll
    for (int i = 0; i < 8; ++i)
        #pragma unroll
        for (int j = 0; j < 8; ++j) acc[i][j] = 0.f;

    const int tx = tid & 15, ty = tid >> 4;

    // stage 0
    {
        float4 av = *(const float4*)&A[(size_t)(m0 + lr) * KDIM + lc];
        float4 bv = *(const float4*)&W[(size_t)(n0 + lr) * KDIM + lc];
        As[0][lc + 0][lr] = av.x; As[0][lc + 1][lr] = av.y;
        As[0][lc + 2][lr] = av.z; As[0][lc + 3][lr] = av.w;
        Bs[0][lc + 0][lr] = bv.x; Bs[0][lc + 1][lr] = bv.y;
        Bs[0][lc + 2][lr] = bv.z; Bs[0][lc + 3][lr] = bv.w;
    }
    __syncthreads();

    int p = 0;
    for (int k0 = 0; k0 < KDIM; k0 += BK) {
        if (k0 + BK < KDIM) {   // load next tile into the other buffer
            float4 av = *(const float4*)&A[(size_t)(m0 + lr) * KDIM + k0 + BK + lc];
            float4 bv = *(const float4*)&W[(size_t)(n0 + lr) * KDIM + k0 + BK + lc];
            As[p ^ 1][lc + 0][lr] = av.x; As[p ^ 1][lc + 1][lr] = av.y;
            As[p ^ 1][lc + 2][lr] = av.z; As[p ^ 1][lc + 3][lr] = av.w;
            Bs[p ^ 1][lc + 0][lr] = bv.x; Bs[p ^ 1][lc + 1][lr] = bv.y;
            Bs[p ^ 1][lc + 2][lr] = bv.z; Bs[p ^ 1][lc + 3][lr] = bv.w;
        }
        #pragma unroll
        for (int kk = 0; kk < BK; ++kk) {
            float4 a0 = *(const float4*)&As[p][kk][ty * 8];
            float4 a1 = *(const float4*)&As[p][kk][ty * 8 + 4];
            float4 b0 = *(const float4*)&Bs[p][kk][tx * 8];
            float4 b1 = *(const float4*)&Bs[p][kk][tx * 8 + 4];
            float a[8] = {a0.x,a0.y,a0.z,a0.w,a1.x,a1.y,a1.z,a1.w};
            float b[8] = {b0.x,b0.y,b0.z,b0.w,b1.x,b1.y,b1.z,b1.w};
            #pragma unroll
            for (int i = 0; i < 8; ++i)
                #pragma unroll
                for (int j = 0; j < 8; ++j)
                    acc[i][j] = fmaf(a[i], b[j], acc[i][j]);
        }
        p ^= 1;
        __syncthreads();
    }

    float bsum[8];
    #pragma unroll
    for (int j = 0; j < 8; ++j) {
        int n = n0 + tx * 8 + j;
        bsum[j] = bi[n] + bh[n];
    }
    #pragma unroll
    for (int i = 0; i < 8; ++i) {
        int m = m0 + ty * 8 + i;
        float* crow = C + (size_t)m * G4 + n0 + tx * 8;
        float4 v0, v1;
        v0.x = acc[i][0] + bsum[0]; v0.y = acc[i][1] + bsum[1];
        v0.z = acc[i][2] + bsum[2]; v0.w = acc[i][3] + bsum[3];
        v1.x = acc[i][4] + bsum[4]; v1.y = acc[i][5] + bsum[5];
        v1.z = acc[i][6] + bsum[6]; v1.w = acc[i][7] + bsum[7];
        *(float4*)&crow[0] = v0;
        *(float4*)&crow[4] = v1;
    }
}

// ---------------- recurrent kernel: one layer, both branches ----------------
// 128 CTAs x 512 threads (16 warps). CTA c owns 8 hidden units (32 gate rows).
// Weights in REGISTERS as f32x2 pairs (ulonglong2); matvec uses fma.rn.f32x2
// (SASS FFMA2: 2 fp32 FMA per issue). h staged per-branch (hsA/hsB) so packed
// k-pairs come straight from LDS.128. Each warp polls only its own k-slice.
// Producer warps bar.arrive; tail warps (0=branch A, 1=branch B) bar.sync.

#define SRED_PAD 33
#define SRED_BUF (16 * SRED_PAD)
// hsA(1024f) + hsB(1024f) + sredA[2][528] + sredB[2][528]
#define REC_SMEM ((2 * HID + 4 * SRED_BUF) * 4)

__device__ __forceinline__ float sigm(float x) {
    return 1.f / (1.f + __expf(-x));
}
__device__ __forceinline__ float tanh_fast(float x) {
    // tanh(x) = 2*sigmoid(2x) - 1, ~1e-6 abs error with __expf
    return __fmaf_rn(2.f, 1.f / (1.f + __expf(-2.f * x)), -1.f);
}

__device__ __forceinline__ void fma2(unsigned long long& acc,
                                     unsigned long long a, unsigned long long b) {
    asm("fma.rn.f32x2 %0, %1, %2, %0;" : "+l"(acc) : "l"(a), "l"(b));
}
__device__ __forceinline__ float2 upk(unsigned long long v) {
    float2 r;
    asm("mov.b64 {%0,%1}, %2;" : "=f"(r.x), "=f"(r.y) : "l"(v));
    return r;
}

__device__ __forceinline__ void publish8(float2* p, float h, unsigned tag) {
    asm volatile("st.volatile.global.v2.f32 [%0], {%1,%2};"
                 :: "l"(p), "f"(h), "f"(__uint_as_float(tag)) : "memory");
}
__device__ __forceinline__ float2 poll8(const float2* p) {
    float2 v;
    asm volatile("ld.volatile.global.v2.f32 {%0,%1}, [%2];"
                 : "=f"(v.x), "=f"(v.y) : "l"(p) : "memory");
    return v;
}

#define BAR_ARRIVE() asm volatile("bar.arrive 1, 512;" ::: "memory")
#define BAR_SYNC()   asm volatile("bar.sync 1, 512;"   ::: "memory")

__global__ void __launch_bounds__(512, 1)
lstm_rec(const float* __restrict__ Whh,     // [4096][1024] this layer
         const float* __restrict__ h0b0, const float* __restrict__ h0b1,
         const float* __restrict__ c0b0, const float* __restrict__ c0b1)
{
    extern __shared__ float smem[];
    float* hsA   = smem;                                // 1024 floats
    float* hsB   = smem + HID;                          // 1024 floats
    float* sredA = smem + 2 * HID;                      // [2][16*33]
    float* sredB = smem + 2 * HID + 2 * SRED_BUF;       // [2][16*33]

    const int tid  = threadIdx.x;
    const int warp = tid >> 5;
    const int lane = tid & 31;
    const int cta  = blockIdx.x;
    const int u0   = cta * 8;

    // ---- weights into registers as packed f32x2 pairs ----
    // row = lane, k in [warp*64, warp*64+64) = 16 ulonglong2 (4 k each)
    const int gr_lane = (lane >> 3) * HID + u0 + (lane & 7);  // global gate row
    ulonglong2 wv[16];
    {
        const ulonglong2* wrow =
            (const ulonglong2*)&Whh[(size_t)gr_lane * KDIM + warp * 64];
        #pragma unroll
        for (int j = 0; j < 16; ++j) wv[j] = __ldg(&wrow[j]);
    }

    // ---- init cell state + publish h^(0) with tag 1 into buffer 0 ----
    float cst = 0.f;   // cA in warp0, cB in warp1 (lanes 0..7)
    if (warp == 0 && lane < 8) {
        cst = c0b0[u0 + lane];
        publish8(&g_pubA[0][u0 + lane], h0b0[u0 + lane], 1u);
    } else if (warp == 1 && lane < 8) {
        cst = c0b1[u0 + lane];
        publish8(&g_pubB[0][u0 + lane], h0b1[u0 + lane], 1u);
    }

    const ulonglong2* hAu = (const ulonglong2*)hsA + warp * 16;  // 64 floats/warp
    const ulonglong2* hBu = (const ulonglong2*)hsB + warp * 16;
    const int uP0 = warp * 64 + lane;        // units this thread polls/stages
    const int uP1 = warp * 64 + 32 + lane;

    for (int t = 0; t < T_SEQ; ++t) {
        const int p = t & 1;
        const unsigned tag = (unsigned)(t + 1);

        float pre = 0.f;
        if (warp == 0)      pre = __ldg(&g_pre[0][t][gr_lane]);
        else if (warp == 1) pre = __ldg(&g_pre[1][t][gr_lane]);

        // ---- poll own slice (4 packets/thread), stage per-branch ----
        {
            const float2* pA = g_pubA[p];
            const float2* pB = g_pubB[p];
            float2 a0, a1, b0, b1;
            bool o0 = false, o1 = false, o2 = false, o3 = false;
            do {
                if (!o0) { a0 = poll8(&pA[uP0]); o0 = (__float_as_uint(a0.y) == tag); }
                if (!o1) { a1 = poll8(&pA[uP1]); o1 = (__float_as_uint(a1.y) == tag); }
                if (!o2) { b0 = poll8(&pB[uP0]); o2 = (__float_as_uint(b0.y) == tag); }
                if (!o3) { b1 = poll8(&pB[uP1]); o3 = (__float_as_uint(b1.y) == tag); }
            } while (!(o0 & o1 & o2 & o3));
            hsA[uP0] = a0.x; hsA[uP1] = a1.x;
            hsB[uP0] = b0.x; hsB[uP1] = b1.x;
        }
        __syncwarp();   // own slice staged; no block barrier needed

        // ---- matvec: FFMA2 over packed k-pairs, h broadcast from own region ----
        unsigned long long aA0 = 0ull, aA1 = 0ull, aB0 = 0ull, aB1 = 0ull;
        #pragma unroll
        for (int j = 0; j < 16; ++j) {
            ulonglong2 ha = hAu[j];   // 4 k values, branch A
            ulonglong2 hb = hBu[j];   // 4 k values, branch B
            fma2(aA0, wv[j].x, ha.x);
            fma2(aA1, wv[j].y, ha.y);
            fma2(aB0, wv[j].x, hb.x);
            fma2(aB1, wv[j].y, hb.y);
        }
        float2 uA0 = upk(aA0), uA1 = upk(aA1);
        float2 uB0 = upk(aB0), uB1 = upk(aB1);
        float accA = (uA0.x + uA0.y) + (uA1.x + uA1.y);
        float accB = (uB0.x + uB0.y) + (uB1.x + uB1.y);

        sredA[p * SRED_BUF + warp * SRED_PAD + lane] = accA;
        sredB[p * SRED_BUF + warp * SRED_PAD + lane] = accB;

        if (warp >= 2) {
            BAR_ARRIVE();   // non-blocking: run ahead to next step's poll
        } else {
            BAR_SYNC();     // tail warps wait for all 16 partials
            const float* sr = (warp == 0) ? &sredA[p * SRED_BUF] : &sredB[p * SRED_BUF];
            float s = pre;
            #pragma unroll
            for (int w = 0; w < 16; ++w) s += sr[w * SRED_PAD + lane];
            // gather gates: unit u needs rows u, 8+u, 16+u, 24+u
            const int u = lane & 7;
            float gi = __shfl_sync(0xffffffffu, s, u);
            float gf = __shfl_sync(0xffffffffu, s, u + 8);
            float gg = __shfl_sync(0xffffffffu, s, u + 16);
            float go = __shfl_sync(0xffffffffu, s, u + 24);
            if (lane < 8) {
                cst = sigm(gf) * cst + sigm(gi) * tanh_fast(gg);
                float hv = sigm(go) * tanh_fast(cst);
                if (warp == 0) {
                    publish8(&g_pubA[p ^ 1][u0 + u], hv, (unsigned)(t + 2));
                    g_hseq[0][t][u0 + u] = hv;
                } else {
                    publish8(&g_pubB[p ^ 1][u0 + u], hv, (unsigned)(t + 2));
                    g_hseq[1][t][u0 + u] = hv;
                }
            }
        }
    }
}

// ---------------- final reduction: out = 5*exp(-sum|o1-o2|) ----------------
__global__ void final_k(float* __restrict__ out)
{
    __shared__ float red[256];
    int tid = threadIdx.x;
    float s = 0.f;
    for (int j = tid; j < HID; j += 256) {
        float a = g_hseq[0][T_SEQ - 1][j];
        float b = g_hseq[1][T_SEQ - 1][j];
        s += fabsf(a - b);
    }
    red[tid] = s;
    __syncthreads();
    for (int w = 128; w > 0; w >>= 1) {
        if (tid < w) red[tid] += red[tid + w];
        __syncthreads();
    }
    if (tid == 0) out[0] = 5.f * expf(-red[0]);
}

// ---------------- launch ----------------
extern "C" void kernel_launch(void* const* d_in, const int* in_sizes, int n_in,
                              void* d_out, int out_size)
{
    const float* s1   = (const float*)d_in[0];
    const float* s2   = (const float*)d_in[1];
    const float* h1_0 = (const float*)d_in[2];
    const float* c1_0 = (const float*)d_in[3];
    const float* h2_0 = (const float*)d_in[4];
    const float* c2_0 = (const float*)d_in[5];
    const float* W_ih = (const float*)d_in[6];  // [2][4096][1024]
    const float* W_hh = (const float*)d_in[7];  // [2][4096][1024]
    const float* b_ih = (const float*)d_in[8];  // [2][4096]
    const float* b_hh = (const float*)d_in[9];  // [2][4096]

    cudaFuncSetAttribute(lstm_rec, cudaFuncAttributeMaxDynamicSharedMemorySize, REC_SMEM);

    dim3 gg(G4 / BN, T_SEQ / BM, 2);

    // layer 0
    sgemm_nt_bias<<<gg, 256>>>(s1, s2, 0, W_ih, b_ih, b_hh);
    reset_pub<<<1, 512>>>();
    lstm_rec<<<REC_NC, 512, REC_SMEM>>>(W_hh, h1_0, h2_0, c1_0, c2_0);

    // layer 1 (input = layer-0 hidden sequence)
    const size_t woff = (size_t)G4 * KDIM;
    sgemm_nt_bias<<<gg, 256>>>(nullptr, nullptr, 1, W_ih + woff, b_ih + G4, b_hh + G4);
    reset_pub<<<1, 512>>>();
    lstm_rec<<<REC_NC, 512, REC_SMEM>>>(W_hh + woff, h1_0 + HID, h2_0 + HID,
                                        c1_0 + HID, c2_0 + HID);

    final_k<<<1, 256>>>((float*)d_out);
}

// round 7
// speedup vs baseline: 1.0689x; 1.0689x over previous
#include <cuda_runtime.h>
#include <math.h>

// Problem constants
#define T_SEQ 4096
#define HID   1024
#define G4    4096   // 4*HID
#define KDIM  1024   // E == H

#define REC_NC 128   // recurrent CTAs (1 per SM, all co-resident)

typedef unsigned long long ull;

// ---------------- device scratch (static, no allocations) ----------------
__device__ float g_pre[2][T_SEQ][G4];                 // input projections (128 MB)
__device__ float g_hseq[2][T_SEQ][HID];               // per-layer hidden sequence
// LL-style publish buffers: per unit an 8B packet {h, tag}; per branch, double-buffered
__device__ __align__(8) float2 g_pubA[2][HID];
__device__ __align__(8) float2 g_pubB[2][HID];

// ---------------- tag reset (before each recurrent launch / replay) ------
__global__ void reset_pub() {
    float2 z = make_float2(0.f, 0.f);
    int i = threadIdx.x;                  // 512 threads
    #pragma unroll
    for (int j = 0; j < 4; ++j) {
        ((float2*)g_pubA)[i + j * 512] = z;
        ((float2*)g_pubB)[i + j * 512] = z;
    }
}

// ---------------- packed f32x2 helpers ----------------
__device__ __forceinline__ void fma2(ull& acc, ull a, ull b) {
    asm("fma.rn.f32x2 %0, %1, %2, %0;" : "+l"(acc) : "l"(a), "l"(b));
}
__device__ __forceinline__ ull dup2(float x) {
    ull r;
    asm("mov.b64 %0, {%1, %1};" : "=l"(r) : "f"(x));
    return r;
}
__device__ __forceinline__ float2 upk(ull v) {
    float2 r;
    asm("mov.b64 {%0, %1}, %2;" : "=f"(r.x), "=f"(r.y) : "l"(v));
    return r;
}

// ---------------- SGEMM: pre[b][t][r] = sum_k A_b[t][k]*W[r][k] + bias ----
// Ping-pong SMEM double buffering; inner product via FFMA2 (fma.rn.f32x2).
// Packed accumulator lanes are exactly the old scalar chains -> bitwise same.
#define BM 128
#define BN 128
#define BK 8

__global__ void __launch_bounds__(256, 2)
sgemm_nt_bias(const float* __restrict__ A0, const float* __restrict__ A1,
              int from_hseq,
              const float* __restrict__ W,
              const float* __restrict__ bi, const float* __restrict__ bh)
{
    __shared__ float As[2][BK][BM];
    __shared__ float Bs[2][BK][BN];

    const int z = blockIdx.z;   // branch
    const float* A = from_hseq ? &g_hseq[z][0][0] : (z ? A1 : A0);
    float* C = &g_pre[z][0][0];

    const int m0 = blockIdx.y * BM;
    const int n0 = blockIdx.x * BN;
    const int tid = threadIdx.x;

    const int lr = tid >> 1;          // 0..127 row within tile
    const int lc = (tid & 1) * 4;     // 0 or 4 within k-tile

    ull acc2[8][4];                   // [mi][nq]: lanes = n pair (2nq, 2nq+1)
    #pragma unroll
    for (int i = 0; i < 8; ++i)
        #pragma unroll
        for (int q = 0; q < 4; ++q) acc2[i][q] = 0ull;

    const int tx = tid & 15, ty = tid >> 4;

    // stage 0
    {
        float4 av = *(const float4*)&A[(size_t)(m0 + lr) * KDIM + lc];
        float4 bv = *(const float4*)&W[(size_t)(n0 + lr) * KDIM + lc];
        As[0][lc + 0][lr] = av.x; As[0][lc + 1][lr] = av.y;
        As[0][lc + 2][lr] = av.z; As[0][lc + 3][lr] = av.w;
        Bs[0][lc + 0][lr] = bv.x; Bs[0][lc + 1][lr] = bv.y;
        Bs[0][lc + 2][lr] = bv.z; Bs[0][lc + 3][lr] = bv.w;
    }
    __syncthreads();

    int p = 0;
    for (int k0 = 0; k0 < KDIM; k0 += BK) {
        if (k0 + BK < KDIM) {   // load next tile into the other buffer
            float4 av = *(const float4*)&A[(size_t)(m0 + lr) * KDIM + k0 + BK + lc];
            float4 bv = *(const float4*)&W[(size_t)(n0 + lr) * KDIM + k0 + BK + lc];
            As[p ^ 1][lc + 0][lr] = av.x; As[p ^ 1][lc + 1][lr] = av.y;
            As[p ^ 1][lc + 2][lr] = av.z; As[p ^ 1][lc + 3][lr] = av.w;
            Bs[p ^ 1][lc + 0][lr] = bv.x; Bs[p ^ 1][lc + 1][lr] = bv.y;
            Bs[p ^ 1][lc + 2][lr] = bv.z; Bs[p ^ 1][lc + 3][lr] = bv.w;
        }
        #pragma unroll
        for (int kk = 0; kk < BK; ++kk) {
            float4 a0 = *(const float4*)&As[p][kk][ty * 8];
            float4 a1 = *(const float4*)&As[p][kk][ty * 8 + 4];
            ulonglong2 b0 = *(const ulonglong2*)&Bs[p][kk][tx * 8];      // n 0..3
            ulonglong2 b1 = *(const ulonglong2*)&Bs[p][kk][tx * 8 + 4];  // n 4..7
            float a[8] = {a0.x,a0.y,a0.z,a0.w,a1.x,a1.y,a1.z,a1.w};
            #pragma unroll
            for (int i = 0; i < 8; ++i) {
                ull ai = dup2(a[i]);
                fma2(acc2[i][0], ai, b0.x);
                fma2(acc2[i][1], ai, b0.y);
                fma2(acc2[i][2], ai, b1.x);
                fma2(acc2[i][3], ai, b1.y);
            }
        }
        p ^= 1;
        __syncthreads();
    }

    float bsum[8];
    #pragma unroll
    for (int j = 0; j < 8; ++j) {
        int n = n0 + tx * 8 + j;
        bsum[j] = bi[n] + bh[n];
    }
    #pragma unroll
    for (int i = 0; i < 8; ++i) {
        int m = m0 + ty * 8 + i;
        float* crow = C + (size_t)m * G4 + n0 + tx * 8;
        float2 u0v = upk(acc2[i][0]), u1v = upk(acc2[i][1]);
        float2 u2v = upk(acc2[i][2]), u3v = upk(acc2[i][3]);
        float4 v0, v1;
        v0.x = u0v.x + bsum[0]; v0.y = u0v.y + bsum[1];
        v0.z = u1v.x + bsum[2]; v0.w = u1v.y + bsum[3];
        v1.x = u2v.x + bsum[4]; v1.y = u2v.y + bsum[5];
        v1.z = u3v.x + bsum[6]; v1.w = u3v.y + bsum[7];
        *(float4*)&crow[0] = v0;
        *(float4*)&crow[4] = v1;
    }
}

// ---------------- recurrent kernel: one layer, both branches ----------------
// (R5 structure, verbatim, except tanhf -> tanh_fast.)
// 128 CTAs x 512 threads (16 warps). CTA c owns 8 hidden units (32 gate rows).
// Weights in REGISTERS: thread (warp w, lane l) holds row l, k in [64w,64w+64).
// Each warp POLLS ITS OWN k-slice of h packets (8 producer CTAs), stages into
// its private hs2 region, __syncwarp, matvec. One __syncthreads per step, then
// the tail is split: warp0 = branch A, warp1 = branch B (8B LL packets each).

#define SRED_PAD 33
#define SRED_BUF (16 * SRED_PAD)
#define REC_SMEM ((HID * 8) + (4 * SRED_BUF * 4))

__device__ __forceinline__ float sigm(float x) {
    return 1.f / (1.f + __expf(-x));
}
__device__ __forceinline__ float tanh_fast(float x) {
    // tanh(x) = 2*sigmoid(2x) - 1, ~1e-6 abs error with __expf
    return __fmaf_rn(2.f, 1.f / (1.f + __expf(-2.f * x)), -1.f);
}

__device__ __forceinline__ void publish8(float2* p, float h, unsigned tag) {
    asm volatile("st.volatile.global.v2.f32 [%0], {%1,%2};"
                 :: "l"(p), "f"(h), "f"(__uint_as_float(tag)) : "memory");
}
__device__ __forceinline__ float2 poll8(const float2* p) {
    float2 v;
    asm volatile("ld.volatile.global.v2.f32 {%0,%1}, [%2];"
                 : "=f"(v.x), "=f"(v.y) : "l"(p) : "memory");
    return v;
}

__global__ void __launch_bounds__(512, 1)
lstm_rec(const float* __restrict__ Whh,     // [4096][1024] this layer
         const float* __restrict__ h0b0, const float* __restrict__ h0b1,
         const float* __restrict__ c0b0, const float* __restrict__ c0b1)
{
    extern __shared__ float smem[];
    float2* hs2   = (float2*)smem;                    // 1024 float2 (hA,hB)
    float*  sredA = smem + 2 * HID;                   // [2][16*33]
    float*  sredB = smem + 2 * HID + 2 * SRED_BUF;    // [2][16*33]

    const int tid  = threadIdx.x;
    const int warp = tid >> 5;
    const int lane = tid & 31;
    const int cta  = blockIdx.x;
    const int u0   = cta * 8;

    // ---- weights into registers: row = lane, k in [warp*64, warp*64+64) ----
    const int gr_lane = (lane >> 3) * HID + u0 + (lane & 7);  // global gate row
    float4 wreg[16];
    {
        const float4* wrow = (const float4*)&Whh[(size_t)gr_lane * KDIM + warp * 64];
        #pragma unroll
        for (int j = 0; j < 16; ++j) wreg[j] = __ldg(&wrow[j]);
    }

    // ---- init cell state + publish h^(0) with tag 1 into buffer 0 ----
    float cst = 0.f;   // cA in warp0, cB in warp1 (lanes 0..7)
    if (warp == 0 && lane < 8) {
        cst = c0b0[u0 + lane];
        publish8(&g_pubA[0][u0 + lane], h0b0[u0 + lane], 1u);
    } else if (warp == 1 && lane < 8) {
        cst = c0b1[u0 + lane];
        publish8(&g_pubB[0][u0 + lane], h0b1[u0 + lane], 1u);
    }

    const float4* h4base = (const float4*)hs2 + warp * 32; // k base = warp*64
    const int uP0 = warp * 64 + lane;        // units this thread polls/stages
    const int uP1 = warp * 64 + 32 + lane;

    for (int t = 0; t < T_SEQ; ++t) {
        const int p = t & 1;
        const unsigned tag = (unsigned)(t + 1);

        float pre = 0.f;
        if (warp == 0)      pre = __ldg(&g_pre[0][t][gr_lane]);
        else if (warp == 1) pre = __ldg(&g_pre[1][t][gr_lane]);

        // ---- poll own slice (4 packets/thread), stage into private region ----
        {
            const float2* pA = g_pubA[p];
            const float2* pB = g_pubB[p];
            float2 a0, a1, b0, b1;
            bool o0 = false, o1 = false, o2 = false, o3 = false;
            do {
                if (!o0) { a0 = poll8(&pA[uP0]); o0 = (__float_as_uint(a0.y) == tag); }
                if (!o1) { a1 = poll8(&pA[uP1]); o1 = (__float_as_uint(a1.y) == tag); }
                if (!o2) { b0 = poll8(&pB[uP0]); o2 = (__float_as_uint(b0.y) == tag); }
                if (!o3) { b1 = poll8(&pB[uP1]); o3 = (__float_as_uint(b1.y) == tag); }
            } while (!(o0 & o1 & o2 & o3));
            hs2[uP0] = make_float2(a0.x, b0.x);
            hs2[uP1] = make_float2(a1.x, b1.x);
        }
        __syncwarp();   // own slice staged; no block barrier needed

        // ---- matvec: weights in regs, h broadcast from own SMEM region ----
        float accA = 0.f, accB = 0.f;
        #pragma unroll
        for (int j = 0; j < 16; ++j) {
            float4 w   = wreg[j];
            float4 h0v = h4base[j * 2];       // units 4j,4j+1: (A,B,A,B)
            float4 h1v = h4base[j * 2 + 1];   // units 4j+2,4j+3
            accA = fmaf(w.x, h0v.x, accA); accB = fmaf(w.x, h0v.y, accB);
            accA = fmaf(w.y, h0v.z, accA); accB = fmaf(w.y, h0v.w, accB);
            accA = fmaf(w.z, h1v.x, accA); accB = fmaf(w.z, h1v.y, accB);
            accA = fmaf(w.w, h1v.z, accA); accB = fmaf(w.w, h1v.w, accB);
        }
        sredA[p * SRED_BUF + warp * SRED_PAD + lane] = accA;
        sredB[p * SRED_BUF + warp * SRED_PAD + lane] = accB;
        __syncthreads();   // sred complete; warps 2..15 run ahead to next poll

        if (warp < 2) {
            const float* sr = (warp == 0) ? &sredA[p * SRED_BUF] : &sredB[p * SRED_BUF];
            float s = pre;
            #pragma unroll
            for (int w = 0; w < 16; ++w) s += sr[w * SRED_PAD + lane];
            // gather gates: unit u needs rows u, 8+u, 16+u, 24+u
            const int u = lane & 7;
            float gi = __shfl_sync(0xffffffffu, s, u);
            float gf = __shfl_sync(0xffffffffu, s, u + 8);
            float gg = __shfl_sync(0xffffffffu, s, u + 16);
            float go = __shfl_sync(0xffffffffu, s, u + 24);
            if (lane < 8) {
                cst = sigm(gf) * cst + sigm(gi) * tanh_fast(gg);
                float hv = sigm(go) * tanh_fast(cst);
                if (warp == 0) {
                    publish8(&g_pubA[p ^ 1][u0 + u], hv, (unsigned)(t + 2));
                    g_hseq[0][t][u0 + u] = hv;
                } else {
                    publish8(&g_pubB[p ^ 1][u0 + u], hv, (unsigned)(t + 2));
                    g_hseq[1][t][u0 + u] = hv;
                }
            }
        }
    }
}

// ---------------- final reduction: out = 5*exp(-sum|o1-o2|) ----------------
__global__ void final_k(float* __restrict__ out)
{
    __shared__ float red[256];
    int tid = threadIdx.x;
    float s = 0.f;
    for (int j = tid; j < HID; j += 256) {
        float a = g_hseq[0][T_SEQ - 1][j];
        float b = g_hseq[1][T_SEQ - 1][j];
        s += fabsf(a - b);
    }
    red[tid] = s;
    __syncthreads();
    for (int w = 128; w > 0; w >>= 1) {
        if (tid < w) red[tid] += red[tid + w];
        __syncthreads();
    }
    if (tid == 0) out[0] = 5.f * expf(-red[0]);
}

// ---------------- launch ----------------
extern "C" void kernel_launch(void* const* d_in, const int* in_sizes, int n_in,
                              void* d_out, int out_size)
{
    const float* s1   = (const float*)d_in[0];
    const float* s2   = (const float*)d_in[1];
    const float* h1_0 = (const float*)d_in[2];
    const float* c1_0 = (const float*)d_in[3];
    const float* h2_0 = (const float*)d_in[4];
    const float* c2_0 = (const float*)d_in[5];
    const float* W_ih = (const float*)d_in[6];  // [2][4096][1024]
    const float* W_hh = (const float*)d_in[7];  // [2][4096][1024]
    const float* b_ih = (const float*)d_in[8];  // [2][4096]
    const float* b_hh = (const float*)d_in[9];  // [2][4096]

    cudaFuncSetAttribute(lstm_rec, cudaFuncAttributeMaxDynamicSharedMemorySize, REC_SMEM);

    dim3 gg(G4 / BN, T_SEQ / BM, 2);

    // layer 0
    sgemm_nt_bias<<<gg, 256>>>(s1, s2, 0, W_ih, b_ih, b_hh);
    reset_pub<<<1, 512>>>();
    lstm_rec<<<REC_NC, 512, REC_SMEM>>>(W_hh, h1_0, h2_0, c1_0, c2_0);

    // layer 1 (input = layer-0 hidden sequence)
    const size_t woff = (size_t)G4 * KDIM;
    sgemm_nt_bias<<<gg, 256>>>(nullptr, nullptr, 1, W_ih + woff, b_ih + G4, b_hh + G4);
    reset_pub<<<1, 512>>>();
    lstm_rec<<<REC_NC, 512, REC_SMEM>>>(W_hh + woff, h1_0 + HID, h2_0 + HID,
                                        c1_0 + HID, c2_0 + HID);

    final_k<<<1, 256>>>((float*)d_out);
}

// round 8
// speedup vs baseline: 1.1275x; 1.0548x over previous
#include <cuda_runtime.h>
#include <math.h>

// Problem constants
#define T_SEQ 4096
#define HID   1024
#define G4    4096   // 4*HID
#define KDIM  1024   // E == H

#define REC_NC 128   // recurrent CTAs (1 per SM, all co-resident)

// ---------------- device scratch (static, no allocations) ----------------
__device__ float g_pre[2][T_SEQ][G4];                 // input projections (128 MB)
__device__ float g_hseq[2][T_SEQ][HID];               // per-layer hidden sequence
// LL-style publish buffers: per unit an 8B packet {h, tag}; per branch, double-buffered
__device__ __align__(8) float2 g_pubA[2][HID];
__device__ __align__(8) float2 g_pubB[2][HID];

// ---------------- tag reset (before each recurrent launch / replay) ------
__global__ void reset_pub() {
    float2 z = make_float2(0.f, 0.f);
    int i = threadIdx.x;                  // 512 threads
    #pragma unroll
    for (int j = 0; j < 4; ++j) {
        ((float2*)g_pubA)[i + j * 512] = z;
        ((float2*)g_pubB)[i + j * 512] = z;
    }
}

// ---------------- SGEMM: pre[b][t][r] = sum_k A_b[t][k]*W[r][k] + bias ----
// Ping-pong SMEM double buffering, BK=16: one __syncthreads per 16 k.
#define BM 128
#define BN 128
#define BK 16

__global__ void __launch_bounds__(256, 2)
sgemm_nt_bias(const float* __restrict__ A0, const float* __restrict__ A1,
              int from_hseq,
              const float* __restrict__ W,
              const float* __restrict__ bi, const float* __restrict__ bh)
{
    __shared__ float As[2][BK][BM];
    __shared__ float Bs[2][BK][BN];

    const int z = blockIdx.z;   // branch
    const float* A = from_hseq ? &g_hseq[z][0][0] : (z ? A1 : A0);
    float* C = &g_pre[z][0][0];

    const int m0 = blockIdx.y * BM;
    const int n0 = blockIdx.x * BN;
    const int tid = threadIdx.x;

    const int lr = tid >> 1;          // 0..127 row within tile
    const int lc = (tid & 1) * 4;     // 0 or 4; each thread also covers lc+8

    float acc[8][8];
    #pragma unroll
    for (int i = 0; i < 8; ++i)
        #pragma unroll
        for (int j = 0; j < 8; ++j) acc[i][j] = 0.f;

    const int tx = tid & 15, ty = tid >> 4;

    // stage 0
    {
        const float* arow = &A[(size_t)(m0 + lr) * KDIM];
        const float* brow = &W[(size_t)(n0 + lr) * KDIM];
        float4 av0 = *(const float4*)&arow[lc];
        float4 av1 = *(const float4*)&arow[lc + 8];
        float4 bv0 = *(const float4*)&brow[lc];
        float4 bv1 = *(const float4*)&brow[lc + 8];
        As[0][lc + 0][lr] = av0.x; As[0][lc + 1][lr] = av0.y;
        As[0][lc + 2][lr] = av0.z; As[0][lc + 3][lr] = av0.w;
        As[0][lc + 8][lr] = av1.x; As[0][lc + 9][lr] = av1.y;
        As[0][lc +10][lr] = av1.z; As[0][lc +11][lr] = av1.w;
        Bs[0][lc + 0][lr] = bv0.x; Bs[0][lc + 1][lr] = bv0.y;
        Bs[0][lc + 2][lr] = bv0.z; Bs[0][lc + 3][lr] = bv0.w;
        Bs[0][lc + 8][lr] = bv1.x; Bs[0][lc + 9][lr] = bv1.y;
        Bs[0][lc +10][lr] = bv1.z; Bs[0][lc +11][lr] = bv1.w;
    }
    __syncthreads();

    int p = 0;
    for (int k0 = 0; k0 < KDIM; k0 += BK) {
        if (k0 + BK < KDIM) {   // load next tile into the other buffer
            const float* arow = &A[(size_t)(m0 + lr) * KDIM + k0 + BK];
            const float* brow = &W[(size_t)(n0 + lr) * KDIM + k0 + BK];
            float4 av0 = *(const float4*)&arow[lc];
            float4 av1 = *(const float4*)&arow[lc + 8];
            float4 bv0 = *(const float4*)&brow[lc];
            float4 bv1 = *(const float4*)&brow[lc + 8];
            As[p ^ 1][lc + 0][lr] = av0.x; As[p ^ 1][lc + 1][lr] = av0.y;
            As[p ^ 1][lc + 2][lr] = av0.z; As[p ^ 1][lc + 3][lr] = av0.w;
            As[p ^ 1][lc + 8][lr] = av1.x; As[p ^ 1][lc + 9][lr] = av1.y;
            As[p ^ 1][lc +10][lr] = av1.z; As[p ^ 1][lc +11][lr] = av1.w;
            Bs[p ^ 1][lc + 0][lr] = bv0.x; Bs[p ^ 1][lc + 1][lr] = bv0.y;
            Bs[p ^ 1][lc + 2][lr] = bv0.z; Bs[p ^ 1][lc + 3][lr] = bv0.w;
            Bs[p ^ 1][lc + 8][lr] = bv1.x; Bs[p ^ 1][lc + 9][lr] = bv1.y;
            Bs[p ^ 1][lc +10][lr] = bv1.z; Bs[p ^ 1][lc +11][lr] = bv1.w;
        }
        #pragma unroll
        for (int kk = 0; kk < BK; ++kk) {
            float4 a0 = *(const float4*)&As[p][kk][ty * 8];
            float4 a1 = *(const float4*)&As[p][kk][ty * 8 + 4];
            float4 b0 = *(const float4*)&Bs[p][kk][tx * 8];
            float4 b1 = *(const float4*)&Bs[p][kk][tx * 8 + 4];
            float a[8] = {a0.x,a0.y,a0.z,a0.w,a1.x,a1.y,a1.z,a1.w};
            float b[8] = {b0.x,b0.y,b0.z,b0.w,b1.x,b1.y,b1.z,b1.w};
            #pragma unroll
            for (int i = 0; i < 8; ++i)
                #pragma unroll
                for (int j = 0; j < 8; ++j)
                    acc[i][j] = fmaf(a[i], b[j], acc[i][j]);
        }
        p ^= 1;
        __syncthreads();
    }

    float bsum[8];
    #pragma unroll
    for (int j = 0; j < 8; ++j) {
        int n = n0 + tx * 8 + j;
        bsum[j] = bi[n] + bh[n];
    }
    #pragma unroll
    for (int i = 0; i < 8; ++i) {
        int m = m0 + ty * 8 + i;
        float* crow = C + (size_t)m * G4 + n0 + tx * 8;
        float4 v0, v1;
        v0.x = acc[i][0] + bsum[0]; v0.y = acc[i][1] + bsum[1];
        v0.z = acc[i][2] + bsum[2]; v0.w = acc[i][3] + bsum[3];
        v1.x = acc[i][4] + bsum[4]; v1.y = acc[i][5] + bsum[5];
        v1.z = acc[i][6] + bsum[6]; v1.w = acc[i][7] + bsum[7];
        *(float4*)&crow[0] = v0;
        *(float4*)&crow[4] = v1;
    }
}

// ---------------- recurrent kernel: one layer, both branches ----------------
// (R5 structure, verbatim.)
// 128 CTAs x 512 threads (16 warps). CTA c owns 8 hidden units (32 gate rows).
// Weights in REGISTERS: thread (warp w, lane l) holds row l, k in [64w,64w+64).
// Each warp POLLS ITS OWN k-slice of h packets (8 producer CTAs), stages into
// its private hs2 region, __syncwarp, matvec. One __syncthreads per step, then
// the tail is split: warp0 = branch A, warp1 = branch B (8B LL packets each).

#define SRED_PAD 33
#define SRED_BUF (16 * SRED_PAD)
#define REC_SMEM ((HID * 8) + (4 * SRED_BUF * 4))

__device__ __forceinline__ float sigm(float x) {
    return 1.f / (1.f + __expf(-x));
}

__device__ __forceinline__ void publish8(float2* p, float h, unsigned tag) {
    asm volatile("st.volatile.global.v2.f32 [%0], {%1,%2};"
                 :: "l"(p), "f"(h), "f"(__uint_as_float(tag)) : "memory");
}
__device__ __forceinline__ float2 poll8(const float2* p) {
    float2 v;
    asm volatile("ld.volatile.global.v2.f32 {%0,%1}, [%2];"
                 : "=f"(v.x), "=f"(v.y) : "l"(p) : "memory");
    return v;
}

__global__ void __launch_bounds__(512, 1)
lstm_rec(const float* __restrict__ Whh,     // [4096][1024] this layer
         const float* __restrict__ h0b0, const float* __restrict__ h0b1,
         const float* __restrict__ c0b0, const float* __restrict__ c0b1)
{
    extern __shared__ float smem[];
    float2* hs2   = (float2*)smem;                    // 1024 float2 (hA,hB)
    float*  sredA = smem + 2 * HID;                   // [2][16*33]
    float*  sredB = smem + 2 * HID + 2 * SRED_BUF;    // [2][16*33]

    const int tid  = threadIdx.x;
    const int warp = tid >> 5;
    const int lane = tid & 31;
    const int cta  = blockIdx.x;
    const int u0   = cta * 8;

    // ---- weights into registers: row = lane, k in [warp*64, warp*64+64) ----
    const int gr_lane = (lane >> 3) * HID + u0 + (lane & 7);  // global gate row
    float4 wreg[16];
    {
        const float4* wrow = (const float4*)&Whh[(size_t)gr_lane * KDIM + warp * 64];
        #pragma unroll
        for (int j = 0; j < 16; ++j) wreg[j] = __ldg(&wrow[j]);
    }

    // ---- init cell state + publish h^(0) with tag 1 into buffer 0 ----
    float cst = 0.f;   // cA in warp0, cB in warp1 (lanes 0..7)
    if (warp == 0 && lane < 8) {
        cst = c0b0[u0 + lane];
        publish8(&g_pubA[0][u0 + lane], h0b0[u0 + lane], 1u);
    } else if (warp == 1 && lane < 8) {
        cst = c0b1[u0 + lane];
        publish8(&g_pubB[0][u0 + lane], h0b1[u0 + lane], 1u);
    }

    const float4* h4base = (const float4*)hs2 + warp * 32; // k base = warp*64
    const int uP0 = warp * 64 + lane;        // units this thread polls/stages
    const int uP1 = warp * 64 + 32 + lane;

    for (int t = 0; t < T_SEQ; ++t) {
        const int p = t & 1;
        const unsigned tag = (unsigned)(t + 1);

        float pre = 0.f;
        if (warp == 0)      pre = __ldg(&g_pre[0][t][gr_lane]);
        else if (warp == 1) pre = __ldg(&g_pre[1][t][gr_lane]);

        // ---- poll own slice (4 packets/thread), stage into private region ----
        {
            const float2* pA = g_pubA[p];
            const float2* pB = g_pubB[p];
            float2 a0, a1, b0, b1;
            bool o0 = false, o1 = false, o2 = false, o3 = false;
            do {
                if (!o0) { a0 = poll8(&pA[uP0]); o0 = (__float_as_uint(a0.y) == tag); }
                if (!o1) { a1 = poll8(&pA[uP1]); o1 = (__float_as_uint(a1.y) == tag); }
                if (!o2) { b0 = poll8(&pB[uP0]); o2 = (__float_as_uint(b0.y) == tag); }
                if (!o3) { b1 = poll8(&pB[uP1]); o3 = (__float_as_uint(b1.y) == tag); }
            } while (!(o0 & o1 & o2 & o3));
            hs2[uP0] = make_float2(a0.x, b0.x);
            hs2[uP1] = make_float2(a1.x, b1.x);
        }
        __syncwarp();   // own slice staged; no block barrier needed

        // ---- matvec: weights in regs, h broadcast from own SMEM region ----
        float accA = 0.f, accB = 0.f;
        #pragma unroll
        for (int j = 0; j < 16; ++j) {
            float4 w   = wreg[j];
            float4 h0v = h4base[j * 2];       // units 4j,4j+1: (A,B,A,B)
            float4 h1v = h4base[j * 2 + 1];   // units 4j+2,4j+3
            accA = fmaf(w.x, h0v.x, accA); accB = fmaf(w.x, h0v.y, accB);
            accA = fmaf(w.y, h0v.z, accA); accB = fmaf(w.y, h0v.w, accB);
            accA = fmaf(w.z, h1v.x, accA); accB = fmaf(w.z, h1v.y, accB);
            accA = fmaf(w.w, h1v.z, accA); accB = fmaf(w.w, h1v.w, accB);
        }
        sredA[p * SRED_BUF + warp * SRED_PAD + lane] = accA;
        sredB[p * SRED_BUF + warp * SRED_PAD + lane] = accB;
        __syncthreads();   // sred complete; warps 2..15 run ahead to next poll

        if (warp < 2) {
            const float* sr = (warp == 0) ? &sredA[p * SRED_BUF] : &sredB[p * SRED_BUF];
            float s = pre;
            #pragma unroll
            for (int w = 0; w < 16; ++w) s += sr[w * SRED_PAD + lane];
            // gather gates: unit u needs rows u, 8+u, 16+u, 24+u
            const int u = lane & 7;
            float gi = __shfl_sync(0xffffffffu, s, u);
            float gf = __shfl_sync(0xffffffffu, s, u + 8);
            float gg = __shfl_sync(0xffffffffu, s, u + 16);
            float go = __shfl_sync(0xffffffffu, s, u + 24);
            if (lane < 8) {
                cst = sigm(gf) * cst + sigm(gi) * tanhf(gg);
                float hv = sigm(go) * tanhf(cst);
                if (warp == 0) {
                    publish8(&g_pubA[p ^ 1][u0 + u], hv, (unsigned)(t + 2));
                    g_hseq[0][t][u0 + u] = hv;
                } else {
                    publish8(&g_pubB[p ^ 1][u0 + u], hv, (unsigned)(t + 2));
                    g_hseq[1][t][u0 + u] = hv;
                }
            }
        }
    }
}

// ---------------- final reduction: out = 5*exp(-sum|o1-o2|) ----------------
__global__ void final_k(float* __restrict__ out)
{
    __shared__ float red[256];
    int tid = threadIdx.x;
    float s = 0.f;
    for (int j = tid; j < HID; j += 256) {
        float a = g_hseq[0][T_SEQ - 1][j];
        float b = g_hseq[1][T_SEQ - 1][j];
        s += fabsf(a - b);
    }
    red[tid] = s;
    __syncthreads();
    for (int w = 128; w > 0; w >>= 1) {
        if (tid < w) red[tid] += red[tid + w];
        __syncthreads();
    }
    if (tid == 0) out[0] = 5.f * expf(-red[0]);
}

// ---------------- launch ----------------
extern "C" void kernel_launch(void* const* d_in, const int* in_sizes, int n_in,
                              void* d_out, int out_size)
{
    const float* s1   = (const float*)d_in[0];
    const float* s2   = (const float*)d_in[1];
    const float* h1_0 = (const float*)d_in[2];
    const float* c1_0 = (const float*)d_in[3];
    const float* h2_0 = (const float*)d_in[4];
    const float* c2_0 = (const float*)d_in[5];
    const float* W_ih = (const float*)d_in[6];  // [2][4096][1024]
    const float* W_hh = (const float*)d_in[7];  // [2][4096][1024]
    const float* b_ih = (const float*)d_in[8];  // [2][4096]
    const float* b_hh = (const float*)d_in[9];  // [2][4096]

    cudaFuncSetAttribute(lstm_rec, cudaFuncAttributeMaxDynamicSharedMemorySize, REC_SMEM);

    dim3 gg(G4 / BN, T_SEQ / BM, 2);

    // layer 0
    sgemm_nt_bias<<<gg, 256>>>(s1, s2, 0, W_ih, b_ih, b_hh);
    reset_pub<<<1, 512>>>();
    lstm_rec<<<REC_NC, 512, REC_SMEM>>>(W_hh, h1_0, h2_0, c1_0, c2_0);

    // layer 1 (input = layer-0 hidden sequence)
    const size_t woff = (size_t)G4 * KDIM;
    sgemm_nt_bias<<<gg, 256>>>(nullptr, nullptr, 1, W_ih + woff, b_ih + G4, b_hh + G4);
    reset_pub<<<1, 512>>>();
    lstm_rec<<<REC_NC, 512, REC_SMEM>>>(W_hh + woff, h1_0 + HID, h2_0 + HID,
                                        c1_0 + HID, c2_0 + HID);

    final_k<<<1, 256>>>((float*)d_out);
}

// round 9
// speedup vs baseline: 1.2329x; 1.0935x over previous
#include <cuda_runtime.h>
#include <cuda_bf16.h>
#include <math.h>

// Problem constants
#define T_SEQ 4096
#define HID   1024
#define G4    4096   // 4*HID
#define KDIM  1024   // E == H
#define KP    3072   // split-bf16 concatenated K

#define REC_NC 128   // recurrent CTAs (1 per SM, all co-resident)

typedef unsigned short u16;
typedef unsigned int   u32;

// ---------------- device scratch (static, no allocations) ----------------
__device__ float g_pre[2][T_SEQ][G4];                 // input projections (128 MB)
__device__ float g_hseq[2][T_SEQ][HID];               // per-layer hidden sequence
__device__ u16 g_Abf[2][(size_t)T_SEQ * KP];          // A' = [Ahi|Alo|Ahi] bf16
__device__ u16 g_Bbf[(size_t)G4 * KP];                // B' = [Bhi|Bhi|Blo] bf16
// LL-style publish buffers: per unit an 8B packet {h, tag}; per branch, double-buffered
__device__ __align__(8) float2 g_pubA[2][HID];
__device__ __align__(8) float2 g_pubB[2][HID];

// ---------------- tag reset (before each recurrent launch / replay) ------
__global__ void reset_pub() {
    float2 z = make_float2(0.f, 0.f);
    int i = threadIdx.x;                  // 512 threads
    #pragma unroll
    for (int j = 0; j < 4; ++j) {
        ((float2*)g_pubA)[i + j * 512] = z;
        ((float2*)g_pubB)[i + j * 512] = z;
    }
}

// ---------------- bf16 split helpers ----------------
__device__ __forceinline__ void split_bf16(float x, u16& hi, u16& lo) {
    __nv_bfloat16 h = __float2bfloat16(x);
    float r = x - __bfloat162float(h);
    __nv_bfloat16 l = __float2bfloat16(r);
    hi = *(u16*)&h; lo = *(u16*)&l;
}

// ---------------- conversion kernels ----------------
// A' rows: [0,1024)=hi, [1024,2048)=lo, [2048,3072)=hi
__global__ void conv_A(const float* __restrict__ A0, const float* __restrict__ A1,
                       int from_hseq)
{
    const int z = blockIdx.z;
    const float* A = from_hseq ? &g_hseq[z][0][0] : (z ? A1 : A0);
    int e = (blockIdx.x * blockDim.x + threadIdx.x) * 4;   // 4 elems/thread
    int m = e >> 10, k = e & 1023;
    float4 x = *(const float4*)&A[e];
    ushort4 hi, lo;
    split_bf16(x.x, hi.x, lo.x);
    split_bf16(x.y, hi.y, lo.y);
    split_bf16(x.z, hi.z, lo.z);
    split_bf16(x.w, hi.w, lo.w);
    u16* row = &g_Abf[z][(size_t)m * KP];
    *(ushort4*)&row[k]        = hi;
    *(ushort4*)&row[1024 + k] = lo;
    *(ushort4*)&row[2048 + k] = hi;
}

// B' rows: [0,1024)=hi, [1024,2048)=hi, [2048,3072)=lo
__global__ void conv_B(const float* __restrict__ W)
{
    int e = (blockIdx.x * blockDim.x + threadIdx.x) * 4;
    int n = e >> 10, k = e & 1023;
    float4 x = *(const float4*)&W[e];
    ushort4 hi, lo;
    split_bf16(x.x, hi.x, lo.x);
    split_bf16(x.y, hi.y, lo.y);
    split_bf16(x.z, hi.z, lo.z);
    split_bf16(x.w, hi.w, lo.w);
    u16* row = &g_Bbf[(size_t)n * KP];
    *(ushort4*)&row[k]        = hi;
    *(ushort4*)&row[1024 + k] = hi;
    *(ushort4*)&row[2048 + k] = lo;
}

// ---------------- HMMA GEMM: pre[z][m][n] = A'[m,:]·B'[n,:] + bi[n]+bh[n] ----
// CTA 128x128, 256 threads = 8 warps (4 m x 2 n), warp tile 32x64.
// mma.sync m16n8k16 bf16 -> fp32. K' = 3072, chunk KC=32, ping-pong SMEM.
#define KC   32
#define KPAD 40   // bf16 per SMEM row (pad: banks 20g+t mod 32, conflict-free)

__global__ void __launch_bounds__(256, 2)
hgemm_bias(const float* __restrict__ bi, const float* __restrict__ bh)
{
    __shared__ u16 As[2][128][KPAD];
    __shared__ u16 Bs[2][128][KPAD];

    const int z  = blockIdx.z;
    const int m0 = blockIdx.y * 128;
    const int n0 = blockIdx.x * 128;
    const int tid  = threadIdx.x;
    const int warp = tid >> 5;
    const int lane = tid & 31;
    const int g = lane >> 2, t = lane & 3;

    const int wm = (warp & 3) * 32;   // warp m-offset in CTA tile
    const int wn = (warp >> 2) * 64;  // warp n-offset

    const u16* Ag = &g_Abf[z][0];
    const u16* Bg = &g_Bbf[0];
    float* C = &g_pre[z][0][0];

    // staging mapping: row = tid>>2 (+64), col8 = (tid&3)*8
    const int srow = tid >> 2;
    const int scol = (tid & 3) * 8;

    float acc[2][8][4];
    #pragma unroll
    for (int i = 0; i < 2; ++i)
        #pragma unroll
        for (int j = 0; j < 8; ++j)
            #pragma unroll
            for (int q = 0; q < 4; ++q) acc[i][j][q] = 0.f;

    // stage chunk 0
    {
        *(float4*)&As[0][srow][scol] =
            *(const float4*)&Ag[(size_t)(m0 + srow) * KP + scol];
        *(float4*)&As[0][srow + 64][scol] =
            *(const float4*)&Ag[(size_t)(m0 + srow + 64) * KP + scol];
        *(float4*)&Bs[0][srow][scol] =
            *(const float4*)&Bg[(size_t)(n0 + srow) * KP + scol];
        *(float4*)&Bs[0][srow + 64][scol] =
            *(const float4*)&Bg[(size_t)(n0 + srow + 64) * KP + scol];
    }
    __syncthreads();

    int p = 0;
    const int NCHUNK = KP / KC;   // 96
    for (int c = 0; c < NCHUNK; ++c) {
        if (c + 1 < NCHUNK) {
            int kc = (c + 1) * KC;
            *(float4*)&As[p ^ 1][srow][scol] =
                *(const float4*)&Ag[(size_t)(m0 + srow) * KP + kc + scol];
            *(float4*)&As[p ^ 1][srow + 64][scol] =
                *(const float4*)&Ag[(size_t)(m0 + srow + 64) * KP + kc + scol];
            *(float4*)&Bs[p ^ 1][srow][scol] =
                *(const float4*)&Bg[(size_t)(n0 + srow) * KP + kc + scol];
            *(float4*)&Bs[p ^ 1][srow + 64][scol] =
                *(const float4*)&Bg[(size_t)(n0 + srow + 64) * KP + kc + scol];
        }
        #pragma unroll
        for (int ks = 0; ks < KC; ks += 16) {
            // A fragments: 2 m-tiles x 4 words
            u32 af[2][4];
            #pragma unroll
            for (int i = 0; i < 2; ++i) {
                int ra = wm + 16 * i + g;
                af[i][0] = *(const u32*)&As[p][ra][ks + 2 * t];
                af[i][1] = *(const u32*)&As[p][ra + 8][ks + 2 * t];
                af[i][2] = *(const u32*)&As[p][ra][ks + 2 * t + 8];
                af[i][3] = *(const u32*)&As[p][ra + 8][ks + 2 * t + 8];
            }
            // B fragments: 8 n-tiles x 2 words; then mma
            #pragma unroll
            for (int j = 0; j < 8; ++j) {
                int rb = wn + 8 * j + g;
                u32 b0 = *(const u32*)&Bs[p][rb][ks + 2 * t];
                u32 b1 = *(const u32*)&Bs[p][rb][ks + 2 * t + 8];
                #pragma unroll
                for (int i = 0; i < 2; ++i) {
                    asm volatile(
                        "mma.sync.aligned.m16n8k16.row.col.f32.bf16.bf16.f32 "
                        "{%0,%1,%2,%3}, {%4,%5,%6,%7}, {%8,%9}, {%0,%1,%2,%3};\n"
                        : "+f"(acc[i][j][0]), "+f"(acc[i][j][1]),
                          "+f"(acc[i][j][2]), "+f"(acc[i][j][3])
                        : "r"(af[i][0]), "r"(af[i][1]), "r"(af[i][2]), "r"(af[i][3]),
                          "r"(b0), "r"(b1));
                }
            }
        }
        p ^= 1;
        __syncthreads();
    }

    // epilogue: bias + store (c0,c1 -> row g; c2,c3 -> row g+8)
    #pragma unroll
    for (int j = 0; j < 8; ++j) {
        int n = n0 + wn + 8 * j + 2 * t;
        float bs0 = __ldg(&bi[n])     + __ldg(&bh[n]);
        float bs1 = __ldg(&bi[n + 1]) + __ldg(&bh[n + 1]);
        #pragma unroll
        for (int i = 0; i < 2; ++i) {
            int m = m0 + wm + 16 * i + g;
            float2 v0 = make_float2(acc[i][j][0] + bs0, acc[i][j][1] + bs1);
            float2 v1 = make_float2(acc[i][j][2] + bs0, acc[i][j][3] + bs1);
            *(float2*)&C[(size_t)m * G4 + n]       = v0;
            *(float2*)&C[(size_t)(m + 8) * G4 + n] = v1;
        }
    }
}

// ---------------- recurrent kernel: one layer, both branches ----------------
// (R5/R8 structure, verbatim.)
#define SRED_PAD 33
#define SRED_BUF (16 * SRED_PAD)
#define REC_SMEM ((HID * 8) + (4 * SRED_BUF * 4))

__device__ __forceinline__ float sigm(float x) {
    return 1.f / (1.f + __expf(-x));
}

__device__ __forceinline__ void publish8(float2* p, float h, unsigned tag) {
    asm volatile("st.volatile.global.v2.f32 [%0], {%1,%2};"
                 :: "l"(p), "f"(h), "f"(__uint_as_float(tag)) : "memory");
}
__device__ __forceinline__ float2 poll8(const float2* p) {
    float2 v;
    asm volatile("ld.volatile.global.v2.f32 {%0,%1}, [%2];"
                 : "=f"(v.x), "=f"(v.y) : "l"(p) : "memory");
    return v;
}

__global__ void __launch_bounds__(512, 1)
lstm_rec(const float* __restrict__ Whh,     // [4096][1024] this layer
         const float* __restrict__ h0b0, const float* __restrict__ h0b1,
         const float* __restrict__ c0b0, const float* __restrict__ c0b1)
{
    extern __shared__ float smem[];
    float2* hs2   = (float2*)smem;                    // 1024 float2 (hA,hB)
    float*  sredA = smem + 2 * HID;                   // [2][16*33]
    float*  sredB = smem + 2 * HID + 2 * SRED_BUF;    // [2][16*33]

    const int tid  = threadIdx.x;
    const int warp = tid >> 5;
    const int lane = tid & 31;
    const int cta  = blockIdx.x;
    const int u0   = cta * 8;

    // ---- weights into registers: row = lane, k in [warp*64, warp*64+64) ----
    const int gr_lane = (lane >> 3) * HID + u0 + (lane & 7);  // global gate row
    float4 wreg[16];
    {
        const float4* wrow = (const float4*)&Whh[(size_t)gr_lane * KDIM + warp * 64];
        #pragma unroll
        for (int j = 0; j < 16; ++j) wreg[j] = __ldg(&wrow[j]);
    }

    // ---- init cell state + publish h^(0) with tag 1 into buffer 0 ----
    float cst = 0.f;   // cA in warp0, cB in warp1 (lanes 0..7)
    if (warp == 0 && lane < 8) {
        cst = c0b0[u0 + lane];
        publish8(&g_pubA[0][u0 + lane], h0b0[u0 + lane], 1u);
    } else if (warp == 1 && lane < 8) {
        cst = c0b1[u0 + lane];
        publish8(&g_pubB[0][u0 + lane], h0b1[u0 + lane], 1u);
    }

    const float4* h4base = (const float4*)hs2 + warp * 32; // k base = warp*64
    const int uP0 = warp * 64 + lane;        // units this thread polls/stages
    const int uP1 = warp * 64 + 32 + lane;

    for (int t = 0; t < T_SEQ; ++t) {
        const int p = t & 1;
        const unsigned tag = (unsigned)(t + 1);

        float pre = 0.f;
        if (warp == 0)      pre = __ldg(&g_pre[0][t][gr_lane]);
        else if (warp == 1) pre = __ldg(&g_pre[1][t][gr_lane]);

        // ---- poll own slice (4 packets/thread), stage into private region ----
        {
            const float2* pA = g_pubA[p];
            const float2* pB = g_pubB[p];
            float2 a0, a1, b0, b1;
            bool o0 = false, o1 = false, o2 = false, o3 = false;
            do {
                if (!o0) { a0 = poll8(&pA[uP0]); o0 = (__float_as_uint(a0.y) == tag); }
                if (!o1) { a1 = poll8(&pA[uP1]); o1 = (__float_as_uint(a1.y) == tag); }
                if (!o2) { b0 = poll8(&pB[uP0]); o2 = (__float_as_uint(b0.y) == tag); }
                if (!o3) { b1 = poll8(&pB[uP1]); o3 = (__float_as_uint(b1.y) == tag); }
            } while (!(o0 & o1 & o2 & o3));
            hs2[uP0] = make_float2(a0.x, b0.x);
            hs2[uP1] = make_float2(a1.x, b1.x);
        }
        __syncwarp();   // own slice staged; no block barrier needed

        // ---- matvec: weights in regs, h broadcast from own SMEM region ----
        float accA = 0.f, accB = 0.f;
        #pragma unroll
        for (int j = 0; j < 16; ++j) {
            float4 w   = wreg[j];
            float4 h0v = h4base[j * 2];       // units 4j,4j+1: (A,B,A,B)
            float4 h1v = h4base[j * 2 + 1];   // units 4j+2,4j+3
            accA = fmaf(w.x, h0v.x, accA); accB = fmaf(w.x, h0v.y, accB);
            accA = fmaf(w.y, h0v.z, accA); accB = fmaf(w.y, h0v.w, accB);
            accA = fmaf(w.z, h1v.x, accA); accB = fmaf(w.z, h1v.y, accB);
            accA = fmaf(w.w, h1v.z, accA); accB = fmaf(w.w, h1v.w, accB);
        }
        sredA[p * SRED_BUF + warp * SRED_PAD + lane] = accA;
        sredB[p * SRED_BUF + warp * SRED_PAD + lane] = accB;
        __syncthreads();   // sred complete; warps 2..15 run ahead to next poll

        if (warp < 2) {
            const float* sr = (warp == 0) ? &sredA[p * SRED_BUF] : &sredB[p * SRED_BUF];
            float s = pre;
            #pragma unroll
            for (int w = 0; w < 16; ++w) s += sr[w * SRED_PAD + lane];
            // gather gates: unit u needs rows u, 8+u, 16+u, 24+u
            const int u = lane & 7;
            float gi = __shfl_sync(0xffffffffu, s, u);
            float gf = __shfl_sync(0xffffffffu, s, u + 8);
            float gg = __shfl_sync(0xffffffffu, s, u + 16);
            float go = __shfl_sync(0xffffffffu, s, u + 24);
            if (lane < 8) {
                cst = sigm(gf) * cst + sigm(gi) * tanhf(gg);
                float hv = sigm(go) * tanhf(cst);
                if (warp == 0) {
                    publish8(&g_pubA[p ^ 1][u0 + u], hv, (unsigned)(t + 2));
                    g_hseq[0][t][u0 + u] = hv;
                } else {
                    publish8(&g_pubB[p ^ 1][u0 + u], hv, (unsigned)(t + 2));
                    g_hseq[1][t][u0 + u] = hv;
                }
            }
        }
    }
}

// ---------------- final reduction: out = 5*exp(-sum|o1-o2|) ----------------
__global__ void final_k(float* __restrict__ out)
{
    __shared__ float red[256];
    int tid = threadIdx.x;
    float s = 0.f;
    for (int j = tid; j < HID; j += 256) {
        float a = g_hseq[0][T_SEQ - 1][j];
        float b = g_hseq[1][T_SEQ - 1][j];
        s += fabsf(a - b);
    }
    red[tid] = s;
    __syncthreads();
    for (int w = 128; w > 0; w >>= 1) {
        if (tid < w) red[tid] += red[tid + w];
        __syncthreads();
    }
    if (tid == 0) out[0] = 5.f * expf(-red[0]);
}

// ---------------- launch ----------------
extern "C" void kernel_launch(void* const* d_in, const int* in_sizes, int n_in,
                              void* d_out, int out_size)
{
    const float* s1   = (const float*)d_in[0];
    const float* s2   = (const float*)d_in[1];
    const float* h1_0 = (const float*)d_in[2];
    const float* c1_0 = (const float*)d_in[3];
    const float* h2_0 = (const float*)d_in[4];
    const float* c2_0 = (const float*)d_in[5];
    const float* W_ih = (const float*)d_in[6];  // [2][4096][1024]
    const float* W_hh = (const float*)d_in[7];  // [2][4096][1024]
    const float* b_ih = (const float*)d_in[8];  // [2][4096]
    const float* b_hh = (const float*)d_in[9];  // [2][4096]

    cudaFuncSetAttribute(lstm_rec, cudaFuncAttributeMaxDynamicSharedMemorySize, REC_SMEM);

    dim3 gConvA(4096, 1, 2);      // 4M elems / (256 thr * 4 elem)
    dim3 gConvB(4096, 1, 1);
    dim3 gGemm(32, 32, 2);

    // layer 0
    conv_A<<<gConvA, 256>>>(s1, s2, 0);
    conv_B<<<gConvB, 256>>>(W_ih);
    hgemm_bias<<<gGemm, 256>>>(b_ih, b_hh);
    reset_pub<<<1, 512>>>();
    lstm_rec<<<REC_NC, 512, REC_SMEM>>>(W_hh, h1_0, h2_0, c1_0, c2_0);

    // layer 1 (input = layer-0 hidden sequence)
    const size_t woff = (size_t)G4 * KDIM;
    conv_A<<<gConvA, 256>>>(nullptr, nullptr, 1);
    conv_B<<<gConvB, 256>>>(W_ih + woff);
    hgemm_bias<<<gGemm, 256>>>(b_ih + G4, b_hh + G4);
    reset_pub<<<1, 512>>>();
    lstm_rec<<<REC_NC, 512, REC_SMEM>>>(W_hh + woff, h1_0 + HID, h2_0 + HID,
                                        c1_0 + HID, c2_0 + HID);

    final_k<<<1, 256>>>((float*)d_out);
}

// round 10
// speedup vs baseline: 1.2616x; 1.0233x over previous
#include <cuda_runtime.h>
#include <cuda_bf16.h>
#include <math.h>

// Problem constants
#define T_SEQ 4096
#define HID   1024
#define G4    4096   // 4*HID
#define KDIM  1024   // E == H
#define KP    3072   // split-bf16 concatenated K

#define REC_NC 128   // recurrent CTAs (1 per SM, all co-resident)

typedef unsigned short u16;
typedef unsigned int   u32;

// ---------------- device scratch (static, no allocations) ----------------
__device__ float g_pre[2][T_SEQ][G4];                 // input projections (128 MB)
__device__ float g_hseq[2][T_SEQ][HID];               // per-layer hidden sequence
__device__ u16 g_Abf[2][(size_t)T_SEQ * KP];          // A' = [Ahi|Alo|Ahi] bf16
__device__ u16 g_Bbf[(size_t)G4 * KP];                // B' = [Bhi|Bhi|Blo] bf16
// LL-style publish buffers: per unit an 8B packet {h, tag}; per branch, double-buffered
__device__ __align__(8) float2 g_pubA[2][HID];
__device__ __align__(8) float2 g_pubB[2][HID];

// ---------------- tag reset (before each recurrent launch / replay) ------
__global__ void reset_pub() {
    float2 z = make_float2(0.f, 0.f);
    int i = threadIdx.x;                  // 512 threads
    #pragma unroll
    for (int j = 0; j < 4; ++j) {
        ((float2*)g_pubA)[i + j * 512] = z;
        ((float2*)g_pubB)[i + j * 512] = z;
    }
}

// ---------------- bf16 split helpers ----------------
__device__ __forceinline__ void split_bf16(float x, u16& hi, u16& lo) {
    __nv_bfloat16 h = __float2bfloat16(x);
    float r = x - __bfloat162float(h);
    __nv_bfloat16 l = __float2bfloat16(r);
    hi = *(u16*)&h; lo = *(u16*)&l;
}

// ---------------- conversion kernels ----------------
// A' rows: [0,1024)=hi, [1024,2048)=lo, [2048,3072)=hi
__global__ void conv_A(const float* __restrict__ A0, const float* __restrict__ A1,
                       int from_hseq)
{
    const int z = blockIdx.z;
    const float* A = from_hseq ? &g_hseq[z][0][0] : (z ? A1 : A0);
    int e = (blockIdx.x * blockDim.x + threadIdx.x) * 4;   // 4 elems/thread
    int m = e >> 10, k = e & 1023;
    float4 x = *(const float4*)&A[e];
    ushort4 hi, lo;
    split_bf16(x.x, hi.x, lo.x);
    split_bf16(x.y, hi.y, lo.y);
    split_bf16(x.z, hi.z, lo.z);
    split_bf16(x.w, hi.w, lo.w);
    u16* row = &g_Abf[z][(size_t)m * KP];
    *(ushort4*)&row[k]        = hi;
    *(ushort4*)&row[1024 + k] = lo;
    *(ushort4*)&row[2048 + k] = hi;
}

// B' rows: [0,1024)=hi, [1024,2048)=hi, [2048,3072)=lo
__global__ void conv_B(const float* __restrict__ W)
{
    int e = (blockIdx.x * blockDim.x + threadIdx.x) * 4;
    int n = e >> 10, k = e & 1023;
    float4 x = *(const float4*)&W[e];
    ushort4 hi, lo;
    split_bf16(x.x, hi.x, lo.x);
    split_bf16(x.y, hi.y, lo.y);
    split_bf16(x.z, hi.z, lo.z);
    split_bf16(x.w, hi.w, lo.w);
    u16* row = &g_Bbf[(size_t)n * KP];
    *(ushort4*)&row[k]        = hi;
    *(ushort4*)&row[1024 + k] = hi;
    *(ushort4*)&row[2048 + k] = lo;
}

// ---------------- HMMA GEMM: pre[z][m][n] = A'[m,:]·B'[n,:] + bi[n]+bh[n] ----
// CTA 128x128, 256 threads = 8 warps (4 m x 2 n), warp tile 32x64.
// mma.sync m16n8k16 bf16 -> fp32. K' = 3072, chunk KC=32, ping-pong SMEM.
// Fragments loaded via ldmatrix.x4 (6 LDSM vs 24 LDS.32 per warp per 16-k).
#define KC   32
#define KPAD 40   // u16 per SMEM row (80B: LDSM segment banks 20r+c cover all 32)
#define BUFB (128 * KPAD * 2)   // bytes per ping-pong buffer (10240)

__device__ __forceinline__ u32 cvta_s(const void* p) {
    return (u32)__cvta_generic_to_shared(p);
}
#define LDSM_X4(r0, r1, r2, r3, addr) \
    asm volatile("ldmatrix.sync.aligned.m8n8.x4.shared.b16 {%0,%1,%2,%3}, [%4];" \
                 : "=r"(r0), "=r"(r1), "=r"(r2), "=r"(r3) : "r"(addr))

__global__ void __launch_bounds__(256, 2)
hgemm_bias(const float* __restrict__ bi, const float* __restrict__ bh)
{
    __shared__ u16 As[2][128][KPAD];
    __shared__ u16 Bs[2][128][KPAD];

    const int z  = blockIdx.z;
    const int m0 = blockIdx.y * 128;
    const int n0 = blockIdx.x * 128;
    const int tid  = threadIdx.x;
    const int warp = tid >> 5;
    const int lane = tid & 31;
    const int g = lane >> 2, t = lane & 3;

    const int wm = (warp & 3) * 32;   // warp m-offset in CTA tile
    const int wn = (warp >> 2) * 64;  // warp n-offset

    const u16* Ag = &g_Abf[z][0];
    const u16* Bg = &g_Bbf[0];
    float* C = &g_pre[z][0][0];

    // staging mapping: row = tid>>2 (+64), col8 = (tid&3)*8
    const int srow = tid >> 2;
    const int scol = (tid & 3) * 8;

    // ldmatrix lane->address mapping (buffer 0; add p*BUFB, i/j, ks offsets)
    // A m16k16 x4: row = base + (lane&15), col = (lane>>4)*8
    const u32 aAddr0 = cvta_s(&As[0][wm + (lane & 15)][(lane >> 4) * 8]);
    // B two m8k16 tiles per x4: row = base + (lane&7) + (lane>>4)*8,
    //                           col = ((lane>>3)&1)*8
    const u32 bAddr0 = cvta_s(&Bs[0][wn + (lane & 7) + ((lane >> 4) * 8)]
                                    [((lane >> 3) & 1) * 8]);

    float acc[2][8][4];
    #pragma unroll
    for (int i = 0; i < 2; ++i)
        #pragma unroll
        for (int j = 0; j < 8; ++j)
            #pragma unroll
            for (int q = 0; q < 4; ++q) acc[i][j][q] = 0.f;

    // stage chunk 0
    {
        *(float4*)&As[0][srow][scol] =
            *(const float4*)&Ag[(size_t)(m0 + srow) * KP + scol];
        *(float4*)&As[0][srow + 64][scol] =
            *(const float4*)&Ag[(size_t)(m0 + srow + 64) * KP + scol];
        *(float4*)&Bs[0][srow][scol] =
            *(const float4*)&Bg[(size_t)(n0 + srow) * KP + scol];
        *(float4*)&Bs[0][srow + 64][scol] =
            *(const float4*)&Bg[(size_t)(n0 + srow + 64) * KP + scol];
    }
    __syncthreads();

    int p = 0;
    const int NCHUNK = KP / KC;   // 96
    for (int c = 0; c < NCHUNK; ++c) {
        if (c + 1 < NCHUNK) {
            int kc = (c + 1) * KC;
            *(float4*)&As[p ^ 1][srow][scol] =
                *(const float4*)&Ag[(size_t)(m0 + srow) * KP + kc + scol];
            *(float4*)&As[p ^ 1][srow + 64][scol] =
                *(const float4*)&Ag[(size_t)(m0 + srow + 64) * KP + kc + scol];
            *(float4*)&Bs[p ^ 1][srow][scol] =
                *(const float4*)&Bg[(size_t)(n0 + srow) * KP + kc + scol];
            *(float4*)&Bs[p ^ 1][srow + 64][scol] =
                *(const float4*)&Bg[(size_t)(n0 + srow + 64) * KP + kc + scol];
        }
        const u32 aBase = aAddr0 + p * BUFB;
        const u32 bBase = bAddr0 + p * BUFB;
        #pragma unroll
        for (int ks = 0; ks < KC; ks += 16) {
            // A fragments: 2 m-tiles, one LDSM.x4 each
            u32 af[2][4];
            #pragma unroll
            for (int i = 0; i < 2; ++i) {
                LDSM_X4(af[i][0], af[i][1], af[i][2], af[i][3],
                        aBase + i * (16 * KPAD * 2) + ks * 2);
            }
            // B fragments: 8 n-tiles as 4 LDSM.x4 (2 tiles each); then mma
            #pragma unroll
            for (int j = 0; j < 8; j += 2) {
                u32 b0, b1, b2, b3;
                LDSM_X4(b0, b1, b2, b3,
                        bBase + j * (8 * KPAD * 2) + ks * 2);
                #pragma unroll
                for (int i = 0; i < 2; ++i) {
                    asm volatile(
                        "mma.sync.aligned.m16n8k16.row.col.f32.bf16.bf16.f32 "
                        "{%0,%1,%2,%3}, {%4,%5,%6,%7}, {%8,%9}, {%0,%1,%2,%3};\n"
                        : "+f"(acc[i][j][0]), "+f"(acc[i][j][1]),
                          "+f"(acc[i][j][2]), "+f"(acc[i][j][3])
                        : "r"(af[i][0]), "r"(af[i][1]), "r"(af[i][2]), "r"(af[i][3]),
                          "r"(b0), "r"(b1));
                    asm volatile(
                        "mma.sync.aligned.m16n8k16.row.col.f32.bf16.bf16.f32 "
                        "{%0,%1,%2,%3}, {%4,%5,%6,%7}, {%8,%9}, {%0,%1,%2,%3};\n"
                        : "+f"(acc[i][j + 1][0]), "+f"(acc[i][j + 1][1]),
                          "+f"(acc[i][j + 1][2]), "+f"(acc[i][j + 1][3])
                        : "r"(af[i][0]), "r"(af[i][1]), "r"(af[i][2]), "r"(af[i][3]),
                          "r"(b2), "r"(b3));
                }
            }
        }
        p ^= 1;
        __syncthreads();
    }

    // epilogue: bias + store (c0,c1 -> row g; c2,c3 -> row g+8)
    #pragma unroll
    for (int j = 0; j < 8; ++j) {
        int n = n0 + wn + 8 * j + 2 * t;
        float bs0 = __ldg(&bi[n])     + __ldg(&bh[n]);
        float bs1 = __ldg(&bi[n + 1]) + __ldg(&bh[n + 1]);
        #pragma unroll
        for (int i = 0; i < 2; ++i) {
            int m = m0 + wm + 16 * i + g;
            float2 v0 = make_float2(acc[i][j][0] + bs0, acc[i][j][1] + bs1);
            float2 v1 = make_float2(acc[i][j][2] + bs0, acc[i][j][3] + bs1);
            *(float2*)&C[(size_t)m * G4 + n]       = v0;
            *(float2*)&C[(size_t)(m + 8) * G4 + n] = v1;
        }
    }
}

// ---------------- recurrent kernel: one layer, both branches ----------------
// (R5/R8 structure, verbatim.)
#define SRED_PAD 33
#define SRED_BUF (16 * SRED_PAD)
#define REC_SMEM ((HID * 8) + (4 * SRED_BUF * 4))

__device__ __forceinline__ float sigm(float x) {
    return 1.f / (1.f + __expf(-x));
}

__device__ __forceinline__ void publish8(float2* p, float h, unsigned tag) {
    asm volatile("st.volatile.global.v2.f32 [%0], {%1,%2};"
                 :: "l"(p), "f"(h), "f"(__uint_as_float(tag)) : "memory");
}
__device__ __forceinline__ float2 poll8(const float2* p) {
    float2 v;
    asm volatile("ld.volatile.global.v2.f32 {%0,%1}, [%2];"
                 : "=f"(v.x), "=f"(v.y) : "l"(p) : "memory");
    return v;
}

__global__ void __launch_bounds__(512, 1)
lstm_rec(const float* __restrict__ Whh,     // [4096][1024] this layer
         const float* __restrict__ h0b0, const float* __restrict__ h0b1,
         const float* __restrict__ c0b0, const float* __restrict__ c0b1)
{
    extern __shared__ float smem[];
    float2* hs2   = (float2*)smem;                    // 1024 float2 (hA,hB)
    float*  sredA = smem + 2 * HID;                   // [2][16*33]
    float*  sredB = smem + 2 * HID + 2 * SRED_BUF;    // [2][16*33]

    const int tid  = threadIdx.x;
    const int warp = tid >> 5;
    const int lane = tid & 31;
    const int cta  = blockIdx.x;
    const int u0   = cta * 8;

    // ---- weights into registers: row = lane, k in [warp*64, warp*64+64) ----
    const int gr_lane = (lane >> 3) * HID + u0 + (lane & 7);  // global gate row
    float4 wreg[16];
    {
        const float4* wrow = (const float4*)&Whh[(size_t)gr_lane * KDIM + warp * 64];
        #pragma unroll
        for (int j = 0; j < 16; ++j) wreg[j] = __ldg(&wrow[j]);
    }

    // ---- init cell state + publish h^(0) with tag 1 into buffer 0 ----
    float cst = 0.f;   // cA in warp0, cB in warp1 (lanes 0..7)
    if (warp == 0 && lane < 8) {
        cst = c0b0[u0 + lane];
        publish8(&g_pubA[0][u0 + lane], h0b0[u0 + lane], 1u);
    } else if (warp == 1 && lane < 8) {
        cst = c0b1[u0 + lane];
        publish8(&g_pubB[0][u0 + lane], h0b1[u0 + lane], 1u);
    }

    const float4* h4base = (const float4*)hs2 + warp * 32; // k base = warp*64
    const int uP0 = warp * 64 + lane;        // units this thread polls/stages
    const int uP1 = warp * 64 + 32 + lane;

    for (int t = 0; t < T_SEQ; ++t) {
        const int p = t & 1;
        const unsigned tag = (unsigned)(t + 1);

        float pre = 0.f;
        if (warp == 0)      pre = __ldg(&g_pre[0][t][gr_lane]);
        else if (warp == 1) pre = __ldg(&g_pre[1][t][gr_lane]);

        // ---- poll own slice (4 packets/thread), stage into private region ----
        {
            const float2* pA = g_pubA[p];
            const float2* pB = g_pubB[p];
            float2 a0, a1, b0, b1;
            bool o0 = false, o1 = false, o2 = false, o3 = false;
            do {
                if (!o0) { a0 = poll8(&pA[uP0]); o0 = (__float_as_uint(a0.y) == tag); }
                if (!o1) { a1 = poll8(&pA[uP1]); o1 = (__float_as_uint(a1.y) == tag); }
                if (!o2) { b0 = poll8(&pB[uP0]); o2 = (__float_as_uint(b0.y) == tag); }
                if (!o3) { b1 = poll8(&pB[uP1]); o3 = (__float_as_uint(b1.y) == tag); }
            } while (!(o0 & o1 & o2 & o3));
            hs2[uP0] = make_float2(a0.x, b0.x);
            hs2[uP1] = make_float2(a1.x, b1.x);
        }
        __syncwarp();   // own slice staged; no block barrier needed

        // ---- matvec: weights in regs, h broadcast from own SMEM region ----
        float accA = 0.f, accB = 0.f;
        #pragma unroll
        for (int j = 0; j < 16; ++j) {
            float4 w   = wreg[j];
            float4 h0v = h4base[j * 2];       // units 4j,4j+1: (A,B,A,B)
            float4 h1v = h4base[j * 2 + 1];   // units 4j+2,4j+3
            accA = fmaf(w.x, h0v.x, accA); accB = fmaf(w.x, h0v.y, accB);
            accA = fmaf(w.y, h0v.z, accA); accB = fmaf(w.y, h0v.w, accB);
            accA = fmaf(w.z, h1v.x, accA); accB = fmaf(w.z, h1v.y, accB);
            accA = fmaf(w.w, h1v.z, accA); accB = fmaf(w.w, h1v.w, accB);
        }
        sredA[p * SRED_BUF + warp * SRED_PAD + lane] = accA;
        sredB[p * SRED_BUF + warp * SRED_PAD + lane] = accB;
        __syncthreads();   // sred complete; warps 2..15 run ahead to next poll

        if (warp < 2) {
            const float* sr = (warp == 0) ? &sredA[p * SRED_BUF] : &sredB[p * SRED_BUF];
            float s = pre;
            #pragma unroll
            for (int w = 0; w < 16; ++w) s += sr[w * SRED_PAD + lane];
            // gather gates: unit u needs rows u, 8+u, 16+u, 24+u
            const int u = lane & 7;
            float gi = __shfl_sync(0xffffffffu, s, u);
            float gf = __shfl_sync(0xffffffffu, s, u + 8);
            float gg = __shfl_sync(0xffffffffu, s, u + 16);
            float go = __shfl_sync(0xffffffffu, s, u + 24);
            if (lane < 8) {
                cst = sigm(gf) * cst + sigm(gi) * tanhf(gg);
                float hv = sigm(go) * tanhf(cst);
                if (warp == 0) {
                    publish8(&g_pubA[p ^ 1][u0 + u], hv, (unsigned)(t + 2));
                    g_hseq[0][t][u0 + u] = hv;
                } else {
                    publish8(&g_pubB[p ^ 1][u0 + u], hv, (unsigned)(t + 2));
                    g_hseq[1][t][u0 + u] = hv;
                }
            }
        }
    }
}

// ---------------- final reduction: out = 5*exp(-sum|o1-o2|) ----------------
__global__ void final_k(float* __restrict__ out)
{
    __shared__ float red[256];
    int tid = threadIdx.x;
    float s = 0.f;
    for (int j = tid; j < HID; j += 256) {
        float a = g_hseq[0][T_SEQ - 1][j];
        float b = g_hseq[1][T_SEQ - 1][j];
        s += fabsf(a - b);
    }
    red[tid] = s;
    __syncthreads();
    for (int w = 128; w > 0; w >>= 1) {
        if (tid < w) red[tid] += red[tid + w];
        __syncthreads();
    }
    if (tid == 0) out[0] = 5.f * expf(-red[0]);
}

// ---------------- launch ----------------
extern "C" void kernel_launch(void* const* d_in, const int* in_sizes, int n_in,
                              void* d_out, int out_size)
{
    const float* s1   = (const float*)d_in[0];
    const float* s2   = (const float*)d_in[1];
    const float* h1_0 = (const float*)d_in[2];
    const float* c1_0 = (const float*)d_in[3];
    const float* h2_0 = (const float*)d_in[4];
    const float* c2_0 = (const float*)d_in[5];
    const float* W_ih = (const float*)d_in[6];  // [2][4096][1024]
    const float* W_hh = (const float*)d_in[7];  // [2][4096][1024]
    const float* b_ih = (const float*)d_in[8];  // [2][4096]
    const float* b_hh = (const float*)d_in[9];  // [2][4096]

    cudaFuncSetAttribute(lstm_rec, cudaFuncAttributeMaxDynamicSharedMemorySize, REC_SMEM);

    dim3 gConvA(4096, 1, 2);      // 4M elems / (256 thr * 4 elem)
    dim3 gConvB(4096, 1, 1);
    dim3 gGemm(32, 32, 2);

    // layer 0
    conv_A<<<gConvA, 256>>>(s1, s2, 0);
    conv_B<<<gConvB, 256>>>(W_ih);
    hgemm_bias<<<gGemm, 256>>>(b_ih, b_hh);
    reset_pub<<<1, 512>>>();
    lstm_rec<<<REC_NC, 512, REC_SMEM>>>(W_hh, h1_0, h2_0, c1_0, c2_0);

    // layer 1 (input = layer-0 hidden sequence)
    const size_t woff = (size_t)G4 * KDIM;
    conv_A<<<gConvA, 256>>>(nullptr, nullptr, 1);
    conv_B<<<gConvB, 256>>>(W_ih + woff);
    hgemm_bias<<<gGemm, 256>>>(b_ih + G4, b_hh + G4);
    reset_pub<<<1, 512>>>();
    lstm_rec<<<REC_NC, 512, REC_SMEM>>>(W_hh + woff, h1_0 + HID, h2_0 + HID,
                                        c1_0 + HID, c2_0 + HID);

    final_k<<<1, 256>>>((float*)d_out);
}